// round 17
// baseline (speedup 1.0000x reference)
#include <cuda_runtime.h>
#include <cuda_bf16.h>
#include <cuda_fp16.h>
#include <cstdint>

#define NN  100000
#define EE  1600000
#define FIN 256
#define HD  128
#define CC  16
#define NB  ((NN + 511) / 512)   // scan blocks = 196

// Scratch (static device globals -- no allocation in kernel_launch)
// INVARIANT: g_cnt is all-zero at kernel_launch entry. It is zero-initialized
// at module load and re-zeroed at the end of every run (in k_final).
__device__ int   g_cnt [NN];
__device__ float g_dinv[NN];
__device__ int   g_off [NN + 1];
__device__ int   g_cur [NN];
__device__ int   g_csr [EE];
__device__ int   g_bsum[NB];
__device__ __align__(16) __half g_hh  [(size_t)NN * HD];   // h2 = dinv*(x@W), fp16
__device__ __align__(16) __half g_acch[(size_t)NN * HD];   // aggregated sums, fp16
__device__ float g_w  [CC * HD];
__device__ float g_b  [CC];
__device__ int   g_i64;
// W in fp16, n-major: [n=128][k=256]
__device__ __align__(16) __half g_wf[HD * FIN];

// ---------------------------------------------------------------------------
// Helpers
// ---------------------------------------------------------------------------
__device__ __forceinline__ uint32_t smem_u32(const void* p) {
    uint32_t a;
    asm("{ .reg .u64 t; cvta.to.shared.u64 t, %1; cvt.u32.u64 %0, t; }" : "=r"(a) : "l"(p));
    return a;
}
#define SW128(o) ((o) ^ (((o) >> 3) & 0x70))

#define LDSM4(r0, r1, r2, r3, a) \
    asm volatile("ldmatrix.sync.aligned.m8n8.x4.shared.b16 {%0,%1,%2,%3}, [%4];" \
                 : "=r"(r0), "=r"(r1), "=r"(r2), "=r"(r3) : "r"(a))

#define MMA_F16(d, a0, a1, a2, a3, b0, b1) \
    asm volatile("mma.sync.aligned.m16n8k16.row.col.f32.f16.f16.f32 " \
                 "{%0,%1,%2,%3}, {%4,%5,%6,%7}, {%8,%9}, {%0,%1,%2,%3};" \
                 : "+f"((d)[0]), "+f"((d)[1]), "+f"((d)[2]), "+f"((d)[3]) \
                 : "r"(a0), "r"(a1), "r"(a2), "r"(a3), "r"(b0), "r"(b1))

// ---------------------------------------------------------------------------
// Detect edge_index dtype (single block; cnt zeroing handled by invariant)
// ---------------------------------------------------------------------------
__global__ void __launch_bounds__(256) k_detect(const unsigned int* __restrict__ w) {
    __shared__ unsigned int s[256];
    int tx = threadIdx.x;
    unsigned int acc = 0;
    #pragma unroll
    for (int j = tx; j < 1024; j += 256) acc |= w[2 * j + 1];
    s[tx] = acc;
    __syncthreads();
    for (int o = 128; o; o >>= 1) {
        if (tx < o) s[tx] |= s[tx + o];
        __syncthreads();
    }
    if (tx == 0) g_i64 = (s[0] == 0u) ? 1 : 0;
}

__device__ __forceinline__ int load_idx(const void* ei, size_t i) {
    return g_i64 ? (int)((const long long*)ei)[i] : ((const int*)ei)[i];
}

__global__ void k_cnt(const void* __restrict__ ei, int e) {
    int i = blockIdx.x * blockDim.x + threadIdx.x;
    if (i < e) atomicAdd(&g_cnt[load_idx(ei, (size_t)e + i)], 1);
}

// ---------------------------------------------------------------------------
// Scan phase 1 (block sums) + dinv computation
// ---------------------------------------------------------------------------
__global__ void __launch_bounds__(512) k_scan1(int n) {
    __shared__ int s[512];
    int b = blockIdx.x, tx = threadIdx.x;
    int i = b * 512 + tx;
    int v = (i < n) ? g_cnt[i] : 0;
    if (i < n) g_dinv[i] = rsqrtf((float)(v + 1));   // +1 self loop
    s[tx] = v;
    __syncthreads();
    for (int o = 256; o; o >>= 1) {
        if (tx < o) s[tx] += s[tx + o];
        __syncthreads();
    }
    if (tx == 0) g_bsum[b] = s[0];
}

// ---------------------------------------------------------------------------
// Scan phase 2+3 fused: each block reduces g_bsum[i<b] for its prefix, then
// scans its local 512 counts. Writes g_off / g_cur.
// ---------------------------------------------------------------------------
__global__ void __launch_bounds__(512) k_scan3(int n, int e) {
    __shared__ int s[512];
    __shared__ int pre;
    int b = blockIdx.x, tx = threadIdx.x;

    s[tx] = (tx < b) ? g_bsum[tx] : 0;
    __syncthreads();
    for (int o = 256; o; o >>= 1) {
        if (tx < o) s[tx] += s[tx + o];
        __syncthreads();
    }
    if (tx == 0) pre = s[0];
    __syncthreads();

    int i = b * 512 + tx;
    int v = (i < n) ? g_cnt[i] : 0;
    s[tx] = v;
    __syncthreads();
    #pragma unroll
    for (int o = 1; o < 512; o <<= 1) {
        int t = (tx >= o) ? s[tx - o] : 0;
        __syncthreads();
        s[tx] += t;
        __syncthreads();
    }
    if (i < n) {
        int excl = s[tx] - v + pre;
        g_off[i] = excl;
        g_cur[i] = excl;
    }
    if (b == 0 && tx == 0) g_off[n] = e;
}

// ---------------------------------------------------------------------------
// CSR fill
// ---------------------------------------------------------------------------
__global__ void k_fill(const void* __restrict__ ei, int e) {
    int i = blockIdx.x * blockDim.x + threadIdx.x;
    if (i >= e) return;
    int s = load_idx(ei, (size_t)i);
    int d = load_idx(ei, (size_t)e + i);
    int p = atomicAdd(&g_cur[d], 1);
    g_csr[p] = s;
}

// ---------------------------------------------------------------------------
// Prep: blocks 0-127 convert W to fp16 (n-major); block 128 samples w/b
// ---------------------------------------------------------------------------
__global__ void __launch_bounds__(256) k_prep(const float* __restrict__ W,
                                              const float* __restrict__ wmu,
                                              const float* __restrict__ wls,
                                              const float* __restrict__ bmu,
                                              const float* __restrict__ bls,
                                              const float* __restrict__ ew,
                                              const float* __restrict__ eb) {
    int tx = threadIdx.x;
    if (blockIdx.x < 128) {
        int idx = blockIdx.x * 256 + tx;   // 0..32767
        int nn = idx >> 8;                 // 0..127
        int k  = idx & 255;                // 0..255
        g_wf[nn * FIN + k] = __float2half(W[(size_t)k * HD + nn]);
    } else {
        for (int i = tx; i < CC * HD; i += 256)
            g_w[i] = wmu[i] + expf(wls[i]) * ew[i];
        if (tx < CC)
            g_b[tx] = bmu[tx] + expf(bls[tx]) * eb[tx];
    }
}

// ---------------------------------------------------------------------------
// Tensor-core GEMM via mma.sync (single fp16 product, fp32 accum):
//   h2[row] = dinv[row] * (x[row] @ W)   -> stored fp16
// ---------------------------------------------------------------------------
#define STAGE   24576
#define OFF_W   8192

__global__ void __launch_bounds__(256) k_mmagemm(const float* __restrict__ x, int n) {
    __shared__ __align__(128) unsigned char sm[2 * STAGE];

    const int tx   = threadIdx.x;
    const int wid  = tx >> 5;
    const int lane = tx & 31;
    const int wr   = wid >> 2;       // 0..1
    const int wc   = wid & 3;        // 0..3
    const int row0 = blockIdx.x * 64;

    const uint32_t base = smem_u32(sm);

    uint32_t aoff[2], boff[2];
    #pragma unroll
    for (int ma = 0; ma < 2; ma++)
        aoff[ma] = (uint32_t)((wr * 32 + ma * 16 + (lane & 15)) * 128 + (lane >> 4) * 16);
    #pragma unroll
    for (int g = 0; g < 2; g++)
        boff[g] = (uint32_t)((wc * 32 + g * 16 + (lane & 15)) * 128 + (lane >> 4) * 16);

    float acc[2][4][4];
    #pragma unroll
    for (int i = 0; i < 2; i++)
        #pragma unroll
        for (int j = 0; j < 4; j++)
            #pragma unroll
            for (int q = 0; q < 4; q++) acc[i][j][q] = 0.f;

    float4 px[4];

    #define LOADX(c) do { \
        _Pragma("unroll") \
        for (int i = 0; i < 4; i++) { \
            int idx = tx + i * 256; \
            int row = idx >> 4, j = idx & 15; \
            int gr  = row0 + row; \
            px[i] = (gr < n) ? *(const float4*)(x + (size_t)gr * FIN + (c) * 64 + 4 * j) \
                             : make_float4(0.f, 0.f, 0.f, 0.f); \
        } } while (0)

    #define STORE(c, s) do { \
        unsigned char* sp = sm + (s) * STAGE; \
        _Pragma("unroll") \
        for (int i = 0; i < 4; i++) { \
            int idx = tx + i * 256; \
            int row = idx >> 4, j = idx & 15; \
            float4 f = px[i]; \
            __half2 p0 = __floats2half2_rn(f.x, f.y); \
            __half2 p1 = __floats2half2_rn(f.z, f.w); \
            uint32_t off = SW128((uint32_t)(row * 128 + 8 * j)); \
            *(uint2*)(sp + off) = make_uint2(*(uint32_t*)&p0, *(uint32_t*)&p1); \
        } \
        _Pragma("unroll") \
        for (int i = 0; i < 4; i++) { \
            int idx = tx + i * 256; \
            int nn = idx >> 3, u = idx & 7; \
            uint32_t off = SW128((uint32_t)(nn * 128 + 16 * u)); \
            *(uint4*)(sp + OFF_W + off) = *(const uint4*)(g_wf + nn * FIN + (c) * 64 + 8 * u); \
        } } while (0)

    LOADX(0);
    STORE(0, 0);
    LOADX(1);

    for (int c = 0; c < 4; c++) {
        __syncthreads();

        {
            uint32_t sb = base + (c & 1) * STAGE;
            #pragma unroll
            for (int ks = 0; ks < 4; ks++) {
                uint32_t ah[2][4];
                #pragma unroll
                for (int ma = 0; ma < 2; ma++) {
                    uint32_t o = SW128(aoff[ma] + ks * 32);
                    LDSM4(ah[ma][0], ah[ma][1], ah[ma][2], ah[ma][3], sb + o);
                }
                #pragma unroll
                for (int g = 0; g < 2; g++) {
                    uint32_t o = SW128(boff[g] + ks * 32);
                    uint32_t b0, b1, b2, b3;
                    LDSM4(b0, b1, b2, b3, sb + OFF_W + o);
                    #pragma unroll
                    for (int ma = 0; ma < 2; ma++) {
                        MMA_F16(acc[ma][2 * g],     ah[ma][0], ah[ma][1], ah[ma][2], ah[ma][3], b0, b2);
                        MMA_F16(acc[ma][2 * g + 1], ah[ma][0], ah[ma][1], ah[ma][2], ah[ma][3], b1, b3);
                    }
                }
            }
        }

        if (c < 3) STORE(c + 1, (c + 1) & 1);
        if (c < 2) LOADX(c + 2);
    }

    // --- Epilogue: scale by dinv[row], store fp16 h2 ---
    #pragma unroll
    for (int ma = 0; ma < 2; ma++) {
        int r1 = row0 + wr * 32 + ma * 16 + (lane >> 2);
        int r2 = r1 + 8;
        float d1 = (r1 < n) ? g_dinv[r1] : 0.f;
        float d2 = (r2 < n) ? g_dinv[r2] : 0.f;
        #pragma unroll
        for (int na = 0; na < 4; na++) {
            int col = wc * 32 + na * 8 + (lane & 3) * 2;
            if (r1 < n) {
                __half2 h = __floats2half2_rn(acc[ma][na][0] * d1, acc[ma][na][1] * d1);
                *(__half2*)&g_hh[(size_t)r1 * HD + col] = h;
            }
            if (r2 < n) {
                __half2 h = __floats2half2_rn(acc[ma][na][2] * d2, acc[ma][na][3] * d2);
                *(__half2*)&g_hh[(size_t)r2 * HD + col] = h;
            }
        }
    }
}

// ---------------------------------------------------------------------------
// Aggregation (pure gather sum): acc[v] = h2[v] + sum_{e: dst=v} h2[csr[e]]
// One warp per node; TWO edges per iteration: lanes 0-15 gather edge j's row
// (uint4 = 16B each), lanes 16-31 edge j+1's. Cross-half combine at the end.
// ---------------------------------------------------------------------------
__device__ __forceinline__ void add8(float* a, uint4 u) {
    __half2 h0 = *(__half2*)&u.x, h1 = *(__half2*)&u.y;
    __half2 h2 = *(__half2*)&u.z, h3 = *(__half2*)&u.w;
    float2 f0 = __half22float2(h0), f1 = __half22float2(h1);
    float2 f2 = __half22float2(h2), f3 = __half22float2(h3);
    a[0] += f0.x; a[1] += f0.y; a[2] += f1.x; a[3] += f1.y;
    a[4] += f2.x; a[5] += f2.y; a[6] += f3.x; a[7] += f3.y;
}

__global__ void __launch_bounds__(256) k_agg(int n) {
    int w    = (blockIdx.x * blockDim.x + threadIdx.x) >> 5;
    int lane = threadIdx.x & 31;
    if (w >= n) return;

    const uint4* hp = reinterpret_cast<const uint4*>(g_hh);   // 16 uint4 per row
    const int half = lane >> 4;        // 0 or 1
    const int col4 = lane & 15;        // uint4 index within row

    float acc[8];
    #pragma unroll
    for (int i = 0; i < 8; i++) acc[i] = 0.f;

    // self loop on the even half
    if (half == 0)
        add8(acc, __ldg(hp + (size_t)w * 16 + col4));

    int e0 = g_off[w], e1 = g_off[w + 1];
    for (int base = e0; base < e1; base += 32) {
        int m   = min(32, e1 - base);
        int idx = (base + lane < e1) ? g_csr[base + lane] : 0;
        int j = 0;
        for (; j + 4 <= m; j += 4) {
            int sA = __shfl_sync(0xffffffffu, idx, j + half);
            int sB = __shfl_sync(0xffffffffu, idx, j + 2 + half);
            uint4 vA = __ldg(hp + (size_t)sA * 16 + col4);
            uint4 vB = __ldg(hp + (size_t)sB * 16 + col4);
            add8(acc, vA);
            add8(acc, vB);
        }
        for (; j + 2 <= m; j += 2) {
            int s = __shfl_sync(0xffffffffu, idx, j + half);
            add8(acc, __ldg(hp + (size_t)s * 16 + col4));
        }
        if (j < m) {   // odd leftover: even half only
            int s = __shfl_sync(0xffffffffu, idx, j);
            if (half == 0)
                add8(acc, __ldg(hp + (size_t)s * 16 + col4));
        }
    }

    // combine the two halves
    #pragma unroll
    for (int i = 0; i < 8; i++)
        acc[i] += __shfl_xor_sync(0xffffffffu, acc[i], 16);

    if (half == 0) {
        __half2 o0 = __floats2half2_rn(acc[0], acc[1]);
        __half2 o1 = __floats2half2_rn(acc[2], acc[3]);
        __half2 o2 = __floats2half2_rn(acc[4], acc[5]);
        __half2 o3 = __floats2half2_rn(acc[6], acc[7]);
        reinterpret_cast<uint4*>(g_acch)[(size_t)w * 16 + col4] =
            make_uint4(*(uint32_t*)&o0, *(uint32_t*)&o1, *(uint32_t*)&o2, *(uint32_t*)&o3);
    }
}

// ---------------------------------------------------------------------------
// Finalize: a = relu(dinv*acc + gcn_b); logits = a @ w^T + b; log_softmax.
// Also re-zeroes g_cnt (restores the entry invariant for the next replay).
// ---------------------------------------------------------------------------
__global__ void __launch_bounds__(256) k_final(const float* __restrict__ gcn_b,
                                               float* __restrict__ out, int n) {
    __shared__ float a_s[16][132];
    __shared__ float w_s[16][132];
    __shared__ float gb[128];
    __shared__ float b_s[16];

    const int tx = threadIdx.x;

    // restore invariant: g_cnt = 0 (grid covers n: 6250 blocks x 256 >= n)
    int z = blockIdx.x * 256 + tx;
    if (z < n) g_cnt[z] = 0;

    #pragma unroll
    for (int i = 0; i < 8; i++) {
        int idx = tx + i * 256;
        w_s[idx >> 7][idx & 127] = g_w[idx];
    }
    if (tx < 128) gb[tx] = gcn_b[tx];
    if (tx < 16)  b_s[tx] = g_b[tx];

    const int n0 = blockIdx.x * 16;
    __syncthreads();

    #pragma unroll
    for (int i = 0; i < 8; i++) {
        int idx  = tx + i * 256;
        int node = idx >> 7, h = idx & 127;
        int g    = n0 + node;
        float v  = 0.f;
        if (g < n)
            v = fmaxf(__half2float(g_acch[(size_t)g * HD + h]) * g_dinv[g] + gb[h], 0.f);
        a_s[node][h] = v;
    }
    __syncthreads();

    const int c    = tx & 15;
    const int node = tx >> 4;

    float lg = b_s[c];
    const float4* ap = (const float4*)&a_s[node][0];
    const float4* wp = (const float4*)&w_s[c][0];
    #pragma unroll
    for (int k = 0; k < 32; k++) {
        float4 av = ap[k];
        float4 wv = wp[k];
        lg += av.x * wv.x + av.y * wv.y + av.z * wv.z + av.w * wv.w;
    }

    float m = lg;
    #pragma unroll
    for (int o = 8; o; o >>= 1) m = fmaxf(m, __shfl_xor_sync(0xffffffffu, m, o));
    float ex = expf(lg - m);
    float ss = ex;
    #pragma unroll
    for (int o = 8; o; o >>= 1) ss += __shfl_xor_sync(0xffffffffu, ss, o);

    if (n0 + node < n)
        out[(size_t)(n0 + node) * CC + c] = lg - m - logf(ss);
}

// ---------------------------------------------------------------------------
extern "C" void kernel_launch(void* const* d_in, const int* in_sizes, int n_in,
                              void* d_out, int out_size) {
    const float* x     = (const float*)d_in[0];
    const void*  ei    = d_in[1];
    const float* W     = (const float*)d_in[2];
    const float* gcn_b = (const float*)d_in[3];
    const float* w_mu  = (const float*)d_in[4];
    const float* w_ls  = (const float*)d_in[5];
    const float* b_mu  = (const float*)d_in[6];
    const float* b_ls  = (const float*)d_in[7];
    const float* eps_w = (const float*)d_in[8];
    const float* eps_b = (const float*)d_in[9];
    float* out = (float*)d_out;

    const int n = in_sizes[0] / FIN;
    const int e = in_sizes[1] / 2;

    static cudaStream_t s1 = nullptr;
    static cudaEvent_t  evF = nullptr, evD = nullptr, evG = nullptr;
    if (!s1) {
        cudaStreamCreateWithFlags(&s1, cudaStreamNonBlocking);
        cudaEventCreateWithFlags(&evF, cudaEventDisableTiming);
        cudaEventCreateWithFlags(&evD, cudaEventDisableTiming);
        cudaEventCreateWithFlags(&evG, cudaEventDisableTiming);
    }

    // fork: prep (W convert + bayes sample) has no dependencies -> s1 immediately
    cudaEventRecord(evF, 0);
    cudaStreamWaitEvent(s1, evF, 0);
    k_prep<<<129, 256, 0, s1>>>(W, w_mu, w_ls, b_mu, b_ls, eps_w, eps_b);

    // main: detect -> cnt -> scan1 produces dinv
    k_detect<<<1, 256>>>((const unsigned int*)ei);
    k_cnt   <<<(e + 255) / 256, 256>>>(ei, e);
    k_scan1 <<<NB, 512>>>(n);
    cudaEventRecord(evD, 0);

    // s1: gemm needs dinv (epilogue prescale)
    cudaStreamWaitEvent(s1, evD, 0);
    k_mmagemm<<<(n + 63) / 64, 256, 0, s1>>>(x, n);
    cudaEventRecord(evG, s1);

    // main: rest of CSR build
    k_scan3<<<NB, 512>>>(n, e);
    k_fill <<<(e + 255) / 256, 256>>>(ei, e);

    // join: aggregation needs CSR + h2
    cudaStreamWaitEvent(0, evG, 0);
    k_agg  <<<(n * 32 + 255) / 256, 256>>>(n);
    k_final<<<(n + 15) / 16, 256>>>(gcn_b, out, n);
}